// round 2
// baseline (speedup 1.0000x reference)
#include <cuda_runtime.h>

// LayerNorm over last axis. [8192 rows, D=1024] fp32, full-shape gamma/beta.
// 2 rows per CTA, 256 threads, all 6 float4 loads issued before the (single)
// barrier so DRAM latency overlaps the reduction.

#define THREADS 256
#define EPS 5e-06f

__global__ __launch_bounds__(THREADS) void layernorm2_kernel(
    const float* __restrict__ input,
    const float* __restrict__ gamma,
    const float* __restrict__ beta,
    float* __restrict__ out)
{
    const int tid = threadIdx.x;
    const long long row0 = (long long)blockIdx.x * 2;
    const long long off0 = row0 * 1024 / 4;        // float4 index of row 0
    const long long off1 = off0 + 256;             // row 1

    const float4* in4 = reinterpret_cast<const float4*>(input);
    const float4* g4  = reinterpret_cast<const float4*>(gamma);
    const float4* b4  = reinterpret_cast<const float4*>(beta);
    float4* out4      = reinterpret_cast<float4*>(out);

    // Issue ALL global loads up front (MLP=6 per thread).
    float4 x0 = in4[off0 + tid];
    float4 x1 = in4[off1 + tid];
    float4 g0 = g4[off0 + tid];
    float4 g1 = g4[off1 + tid];
    float4 b0 = b4[off0 + tid];
    float4 b1 = b4[off1 + tid];

    // Per-thread partials for both rows.
    float s0  = x0.x + x0.y + x0.z + x0.w;
    float ss0 = x0.x * x0.x + x0.y * x0.y + x0.z * x0.z + x0.w * x0.w;
    float s1  = x1.x + x1.y + x1.z + x1.w;
    float ss1 = x1.x * x1.x + x1.y * x1.y + x1.z * x1.z + x1.w * x1.w;

    // Warp reductions.
    #pragma unroll
    for (int off = 16; off > 0; off >>= 1) {
        s0  += __shfl_xor_sync(0xFFFFFFFFu, s0,  off);
        ss0 += __shfl_xor_sync(0xFFFFFFFFu, ss0, off);
        s1  += __shfl_xor_sync(0xFFFFFFFFu, s1,  off);
        ss1 += __shfl_xor_sync(0xFFFFFFFFu, ss1, off);
    }

    // One barrier: leaders publish, everyone reduces the 8 partials locally.
    __shared__ float sh_s0[8], sh_ss0[8], sh_s1[8], sh_ss1[8];
    const int warp = tid >> 5;
    const int lane = tid & 31;
    if (lane == 0) {
        sh_s0[warp]  = s0;  sh_ss0[warp] = ss0;
        sh_s1[warp]  = s1;  sh_ss1[warp] = ss1;
    }
    __syncthreads();

    float ts0 = 0.f, tss0 = 0.f, ts1 = 0.f, tss1 = 0.f;
    #pragma unroll
    for (int i = 0; i < 8; i++) {
        ts0  += sh_s0[i];   tss0 += sh_ss0[i];
        ts1  += sh_s1[i];   tss1 += sh_ss1[i];
    }

    const float invD = 1.0f / 1024.0f;
    const float mean0 = ts0 * invD;
    const float mean1 = ts1 * invD;
    const float rstd0 = rsqrtf(tss0 * invD - mean0 * mean0 + EPS);
    const float rstd1 = rsqrtf(tss1 * invD - mean1 * mean1 + EPS);

    float4 o0, o1;
    o0.x = (x0.x - mean0) * rstd0 * g0.x + b0.x;
    o0.y = (x0.y - mean0) * rstd0 * g0.y + b0.y;
    o0.z = (x0.z - mean0) * rstd0 * g0.z + b0.z;
    o0.w = (x0.w - mean0) * rstd0 * g0.w + b0.w;
    o1.x = (x1.x - mean1) * rstd1 * g1.x + b1.x;
    o1.y = (x1.y - mean1) * rstd1 * g1.y + b1.y;
    o1.z = (x1.z - mean1) * rstd1 * g1.z + b1.z;
    o1.w = (x1.w - mean1) * rstd1 * g1.w + b1.w;

    out4[off0 + tid] = o0;
    out4[off1 + tid] = o1;
}

extern "C" void kernel_launch(void* const* d_in, const int* in_sizes, int n_in,
                              void* d_out, int out_size) {
    const float* input = (const float*)d_in[0];
    const float* gamma = (const float*)d_in[1];
    const float* beta  = (const float*)d_in[2];
    float* out = (float*)d_out;

    const int rows = out_size / 1024;   // 8192
    layernorm2_kernel<<<rows / 2, THREADS>>>(input, gamma, beta, out);
}

// round 3
// speedup vs baseline: 1.0784x; 1.0784x over previous
#include <cuda_runtime.h>

// LayerNorm over last axis. [8192 rows, D=1024] fp32, full-shape gamma/beta.
// Warp-per-row: 32 lanes x 8 float4 = 1024 elems. No smem, no __syncthreads.
// Input loaded fully up front (MLP=8); gamma/beta software-pipelined 2 chunks
// ahead. Streaming cache hints (touch-once data).

#define THREADS 256
#define ROWS_PER_CTA 8   // = THREADS/32
#define EPS 5e-06f

__global__ __launch_bounds__(THREADS) void layernorm_warp_kernel(
    const float4* __restrict__ in4,
    const float4* __restrict__ g4,
    const float4* __restrict__ b4,
    float4* __restrict__ out4)
{
    const int lane = threadIdx.x & 31;
    const int warp = threadIdx.x >> 5;
    const long long row  = (long long)blockIdx.x * ROWS_PER_CTA + warp;
    const long long base = row * 256;           // float4 units per row

    // ---- Load the whole row of input up front (8 independent LDG.128). ----
    float4 x[8];
    #pragma unroll
    for (int i = 0; i < 8; i++)
        x[i] = __ldcs(&in4[base + i * 32 + lane]);

    // ---- Prefetch first gamma/beta chunks so they fly during the reduce. ----
    float4 g[8], b[8];
    #pragma unroll
    for (int i = 0; i < 2; i++) {
        g[i] = __ldcs(&g4[base + i * 32 + lane]);
        b[i] = __ldcs(&b4[base + i * 32 + lane]);
    }

    // ---- Per-lane partial sums over the 8 chunks. ----
    float s = 0.f, ss = 0.f;
    #pragma unroll
    for (int i = 0; i < 8; i++) {
        s  += x[i].x + x[i].y + x[i].z + x[i].w;
        ss += x[i].x * x[i].x + x[i].y * x[i].y
            + x[i].z * x[i].z + x[i].w * x[i].w;
    }

    // ---- Warp-only reduction (no barrier anywhere). ----
    #pragma unroll
    for (int off = 16; off > 0; off >>= 1) {
        s  += __shfl_xor_sync(0xFFFFFFFFu, s,  off);
        ss += __shfl_xor_sync(0xFFFFFFFFu, ss, off);
    }

    const float invD = 1.0f / 1024.0f;
    const float mean = s * invD;
    const float rstd = rsqrtf(ss * invD - mean * mean + EPS);

    // ---- Main loop: prefetch g/b 2 chunks ahead, compute, streaming store. ----
    #pragma unroll
    for (int i = 0; i < 8; i++) {
        if (i + 2 < 8) {
            g[i + 2] = __ldcs(&g4[base + (i + 2) * 32 + lane]);
            b[i + 2] = __ldcs(&b4[base + (i + 2) * 32 + lane]);
        }
        float4 o;
        o.x = (x[i].x - mean) * rstd * g[i].x + b[i].x;
        o.y = (x[i].y - mean) * rstd * g[i].y + b[i].y;
        o.z = (x[i].z - mean) * rstd * g[i].z + b[i].z;
        o.w = (x[i].w - mean) * rstd * g[i].w + b[i].w;
        __stcs(&out4[base + i * 32 + lane], o);
    }
}

extern "C" void kernel_launch(void* const* d_in, const int* in_sizes, int n_in,
                              void* d_out, int out_size) {
    const float4* input = (const float4*)d_in[0];
    const float4* gamma = (const float4*)d_in[1];
    const float4* beta  = (const float4*)d_in[2];
    float4* out = (float4*)d_out;

    const int rows = out_size / 1024;          // 8192
    layernorm_warp_kernel<<<rows / ROWS_PER_CTA, THREADS>>>(input, gamma, beta, out);
}

// round 4
// speedup vs baseline: 1.1951x; 1.1082x over previous
#include <cuda_runtime.h>

// LayerNorm over last axis. [8192 rows, D=1024] fp32, full-shape gamma/beta.
// Warp-per-row, two-pass with L1 reload:
//   pass 1: accumulate sum/sumsq chunk-by-chunk (input cached in L1, not regs)
//   pass 2: re-load input from L1 (__ldca), stream gamma/beta (__ldcs), store.
// Low register footprint -> 6 CTAs/SM -> 48 resident warps keeps DRAM saturated.

#define THREADS 256
#define ROWS_PER_CTA 8   // = THREADS/32
#define EPS 5e-06f

__global__ __launch_bounds__(THREADS, 6) void layernorm_l1_kernel(
    const float4* __restrict__ in4,
    const float4* __restrict__ g4,
    const float4* __restrict__ b4,
    float4* __restrict__ out4)
{
    const int lane = threadIdx.x & 31;
    const int warp = threadIdx.x >> 5;
    const long long row  = (long long)blockIdx.x * ROWS_PER_CTA + warp;
    const long long base = row * 256 + lane;    // float4 units

    // ---- Pass 1: sum / sumsq. Default caching -> row lands in L1. ----
    float s = 0.f, ss = 0.f;
    #pragma unroll
    for (int i = 0; i < 8; i++) {
        float4 v = in4[base + i * 32];
        s  += v.x + v.y + v.z + v.w;
        ss += v.x * v.x + v.y * v.y + v.z * v.z + v.w * v.w;
    }

    // ---- Warp-only reduction (no smem, no barriers). ----
    #pragma unroll
    for (int off = 16; off > 0; off >>= 1) {
        s  += __shfl_xor_sync(0xFFFFFFFFu, s,  off);
        ss += __shfl_xor_sync(0xFFFFFFFFu, ss, off);
    }

    const float invD = 1.0f / 1024.0f;
    const float mean = s * invD;
    const float rstd = rsqrtf(ss * invD - mean * mean + EPS);

    // ---- Pass 2: reload x from L1, stream g/b, fuse, streaming store. ----
    #pragma unroll
    for (int i = 0; i < 8; i++) {
        float4 v = __ldca(&in4[base + i * 32]);   // L1 hit (warm from pass 1)
        float4 g = __ldcs(&g4[base + i * 32]);    // touch-once: evict-first
        float4 b = __ldcs(&b4[base + i * 32]);
        float4 o;
        o.x = (v.x - mean) * rstd * g.x + b.x;
        o.y = (v.y - mean) * rstd * g.y + b.y;
        o.z = (v.z - mean) * rstd * g.z + b.z;
        o.w = (v.w - mean) * rstd * g.w + b.w;
        __stcs(&out4[base + i * 32], o);
    }
}

extern "C" void kernel_launch(void* const* d_in, const int* in_sizes, int n_in,
                              void* d_out, int out_size) {
    const float4* input = (const float4*)d_in[0];
    const float4* gamma = (const float4*)d_in[1];
    const float4* beta  = (const float4*)d_in[2];
    float4* out = (float4*)d_out;

    const int rows = out_size / 1024;          // 8192
    layernorm_l1_kernel<<<rows / ROWS_PER_CTA, THREADS>>>(input, gamma, beta, out);
}